// round 2
// baseline (speedup 1.0000x reference)
#include <cuda_runtime.h>
#include <cstdint>

#define N      2048
#define DIN    256
#define PROJC  256
#define TM     16
#define JB     16           // j's per stage
#define STAGES 3
#define NSTAGE (N / JB)     // 128

// 2 MB scratch for projection output: cols = [Q(64) | K(64) | V(64) | R(64)]
__device__ float g_proj[N * PROJC];

// ---------------------------------------------------------------------------
// Kernel 1: proj = H @ W^T
// ---------------------------------------------------------------------------
__global__ __launch_bounds__(256) void proj_kernel(const float* __restrict__ H,
                                                   const float* __restrict__ W,
                                                   float* __restrict__ proj) {
    __shared__ float Hsh[TM][64];
    extern __shared__ float Wsh[];          // [256][65]
    const int t  = threadIdx.x;
    const int i0 = blockIdx.x * TM;

    float acc[TM];
#pragma unroll
    for (int i = 0; i < TM; i++) acc[i] = 0.f;

    for (int kc = 0; kc < DIN; kc += 64) {
#pragma unroll
        for (int r = 0; r < 4; r++) {
            int idx = t + r * 256;
            Hsh[idx >> 6][idx & 63] = H[(i0 + (idx >> 6)) * DIN + kc + (idx & 63)];
        }
#pragma unroll 8
        for (int r = 0; r < 64; r++) {
            int idx = t + r * 256;
            Wsh[(idx >> 6) * 65 + (idx & 63)] = W[(idx >> 6) * DIN + kc + (idx & 63)];
        }
        __syncthreads();
#pragma unroll
        for (int k = 0; k < 64; k++) {
            float w = Wsh[t * 65 + k];
#pragma unroll
            for (int i = 0; i < TM; i++) acc[i] = fmaf(Hsh[i][k], w, acc[i]);
        }
        __syncthreads();
    }
#pragma unroll
    for (int i = 0; i < TM; i++) proj[(i0 + i) * PROJC + t] = acc[i];
}

// ---------------------------------------------------------------------------
__device__ __forceinline__ float combine2(float a, float b, int mask, int l) {
    float sel = (l & mask) ? a : b;
    float t = __shfl_xor_sync(0xffffffffu, sel, mask);
    return (l & mask) ? (b + t) : (a + t);
}

__device__ __forceinline__ void cp16(uint32_t s, const void* g) {
    asm volatile("cp.async.cg.shared.global [%0], [%1], 16;\n" :: "r"(s), "l"(g));
}

// ---------------------------------------------------------------------------
// Kernel 2: fused scores + ONLINE softmax + attn@V, D staged via cp.async.
// 512 threads. Phase 1 (scores): warp w -> rows (w>>3)*8..+7, jloc {w&7, (w&7)+8},
// lane l owns dims {2l,2l+1}. Phase 2 (softmax/AV): warp w owns query row w.
// ---------------------------------------------------------------------------
__global__ __launch_bounds__(512, 1) void attn_kernel(const float* __restrict__ D,
                                                      const float* __restrict__ proj,
                                                      float* __restrict__ out) {
    extern __shared__ float smem[];
    float* Ds = smem;                              // [STAGES][TM][JB][64]
    float* sc = smem + STAGES * TM * JB * 64;      // [TM][17]

    const int t  = threadIdx.x;
    const int w  = t >> 5;
    const int l  = t & 31;
    const int i0 = blockIdx.x * TM;
    const int rh = (w >> 3) * 8;                   // row half base
    const int jA = w & 7;

    const float scale = 0.08838834764831845f;      // 1/sqrt(DK+DR)

    const uint32_t ds_base = (uint32_t)__cvta_generic_to_shared(Ds);

    // precompute cp.async per-thread mapping (8 x 16B per stage)
    // flat idx = t + kk*512 over 4096: g=idx&15, jloc=(idx>>4)&15, row=idx>>8
    uint32_t s_off[8];
    const float* g_base[8];
#pragma unroll
    for (int kk = 0; kk < 8; kk++) {
        int idx  = t + kk * 512;
        int g    = idx & 15;
        int jloc = (idx >> 4) & 15;
        int row  = idx >> 8;
        s_off[kk]  = (uint32_t)(((row * JB + jloc) * 64 + g * 4) * 4);
        g_base[kk] = D + ((size_t)(i0 + row) * N + jloc) * 64 + g * 4;
    }

    // issue stages 0 and 1
#pragma unroll
    for (int ps = 0; ps < STAGES - 1; ps++) {
        uint32_t sb = ds_base + (uint32_t)(ps * TM * JB * 64 * 4);
#pragma unroll
        for (int kk = 0; kk < 8; kk++)
            cp16(sb + s_off[kk], g_base[kk] + (size_t)ps * JB * 64);
        asm volatile("cp.async.commit_group;\n" ::: "memory");
    }

    // per-lane pre-scaled Q,R fragments for this warp's 8 rows
    float2 q2[8], r2[8];
#pragma unroll
    for (int i = 0; i < 8; i++) {
        const float* row = proj + (size_t)(i0 + rh + i) * PROJC;
        float2 qq = *(const float2*)(row + 2 * l);
        float2 rr = *(const float2*)(row + 192 + 2 * l);
        q2[i] = make_float2(qq.x * scale, qq.y * scale);
        r2[i] = make_float2(rr.x * scale, rr.y * scale);
    }

    const int irow = ((l >> 4) & 1) | (((l >> 3) & 1) << 1) | (((l >> 2) & 1) << 2);

    float  m    = -1e30f;
    float  ssum = 0.f;
    float2 acc  = make_float2(0.f, 0.f);

    for (int k = 0; k < NSTAGE; k++) {
        asm volatile("cp.async.wait_group 1;\n" ::: "memory");
        __syncthreads();

        // -------- phase 1: scores for stage k --------
        const int   b   = k % STAGES;
        const float* Db = Ds + b * TM * JB * 64;
#pragma unroll
        for (int jj = 0; jj < 2; jj++) {
            const int jloc = jA + jj * 8;
            float2 kv = *(const float2*)(proj + (size_t)(k * JB + jloc) * PROJC + 64 + 2 * l);
            float v[8];
#pragma unroll
            for (int r = 0; r < 8; r++) {
                float2 dv = *(const float2*)(Db + ((rh + r) * JB + jloc) * 64 + 2 * l);
                v[r] = fmaf(dv.x, r2[r].x,
                       fmaf(dv.y, r2[r].y,
                       fmaf(kv.x, q2[r].x, kv.y * q2[r].y)));
            }
            float c0 = combine2(v[0], v[1], 16, l);
            float c1 = combine2(v[2], v[3], 16, l);
            float c2 = combine2(v[4], v[5], 16, l);
            float c3 = combine2(v[6], v[7], 16, l);
            float d0 = combine2(c0, c1, 8, l);
            float d1 = combine2(c2, c3, 8, l);
            float e0 = combine2(d0, d1, 4, l);
            float f  = e0 + __shfl_xor_sync(0xffffffffu, e0, 2);
            float g  = f + __shfl_xor_sync(0xffffffffu, f, 1);
            if ((l & 3) == 0) sc[(rh + irow) * 17 + jloc] = g;
        }
        __syncthreads();

        // -------- issue stage k+2 (overlaps with phase 2) --------
        if (k + STAGES - 1 < NSTAGE) {
            const int ns = k + STAGES - 1;
            uint32_t sb = ds_base + (uint32_t)((ns % STAGES) * TM * JB * 64 * 4);
#pragma unroll
            for (int kk = 0; kk < 8; kk++)
                cp16(sb + s_off[kk], g_base[kk] + (size_t)ns * JB * 64);
        }
        asm volatile("cp.async.commit_group;\n" ::: "memory");

        // -------- phase 2: online softmax + P@V, warp w owns row w --------
        float m_blk = -1e30f;
#pragma unroll
        for (int j = 0; j < JB; j++) m_blk = fmaxf(m_blk, sc[w * 17 + j]);
        float m_new = fmaxf(m, m_blk);
        float fsc   = __expf(m - m_new);
        acc.x *= fsc; acc.y *= fsc; ssum *= fsc;
        m = m_new;
#pragma unroll
        for (int j = 0; j < JB; j++) {
            float p = __expf(sc[w * 17 + j] - m);
            ssum += p;
            float2 vv = *(const float2*)(proj + (size_t)(k * JB + j) * PROJC + 128 + 2 * l);
            acc.x = fmaf(p, vv.x, acc.x);
            acc.y = fmaf(p, vv.y, acc.y);
        }
    }

    const float rinv = 1.0f / ssum;
    float2 o = make_float2(acc.x * rinv, acc.y * rinv);
    *(float2*)(out + (size_t)(i0 + w) * 64 + 2 * l) = o;
}

// ---------------------------------------------------------------------------
extern "C" void kernel_launch(void* const* d_in, const int* in_sizes, int n_in,
                              void* d_out, int out_size) {
    const float* H = (const float*)d_in[0];
    const float* D = (const float*)d_in[1];
    const float* W = (const float*)d_in[2];
    float* out = (float*)d_out;

    const int proj_smem = 256 * 65 * 4;                                   // 66,560 B
    const int attn_smem = (STAGES * TM * JB * 64 + TM * 17) * 4;          // 197,696 B
    cudaFuncSetAttribute(proj_kernel, cudaFuncAttributeMaxDynamicSharedMemorySize, proj_smem);
    cudaFuncSetAttribute(attn_kernel, cudaFuncAttributeMaxDynamicSharedMemorySize, attn_smem);

    void* proj_ptr = nullptr;
    cudaGetSymbolAddress(&proj_ptr, g_proj);
    float* proj = (float*)proj_ptr;

    proj_kernel<<<N / TM, 256, proj_smem>>>(H, W, proj);
    attn_kernel<<<N / TM, 512, attn_smem>>>(D, proj, out);
}

// round 3
// speedup vs baseline: 1.8957x; 1.8957x over previous
#include <cuda_runtime.h>
#include <cstdint>

#define N      2048
#define DIN    256
#define PROJC  256
#define PTM    16          // proj kernel row tile
#define TM     8           // attn rows per CTA
#define NW     16          // warps per attn CTA
#define STAGES 4
#define NIT    (N / 16)    // 128 iterations, j = w + 16k

// 2 MB scratch for projection output: cols = [Q(64) | K(64) | V(64) | R(64)]
__device__ float g_proj[N * PROJC];

// ---------------------------------------------------------------------------
// Kernel 1: proj = H @ W^T
// ---------------------------------------------------------------------------
__global__ __launch_bounds__(256) void proj_kernel(const float* __restrict__ H,
                                                   const float* __restrict__ W,
                                                   float* __restrict__ proj) {
    __shared__ float Hsh[PTM][64];
    extern __shared__ float Wsh[];          // [256][65]
    const int t  = threadIdx.x;
    const int i0 = blockIdx.x * PTM;

    float acc[PTM];
#pragma unroll
    for (int i = 0; i < PTM; i++) acc[i] = 0.f;

    for (int kc = 0; kc < DIN; kc += 64) {
#pragma unroll
        for (int r = 0; r < 4; r++) {
            int idx = t + r * 256;
            Hsh[idx >> 6][idx & 63] = H[(i0 + (idx >> 6)) * DIN + kc + (idx & 63)];
        }
#pragma unroll 8
        for (int r = 0; r < 64; r++) {
            int idx = t + r * 256;
            Wsh[(idx >> 6) * 65 + (idx & 63)] = W[(idx >> 6) * DIN + kc + (idx & 63)];
        }
        __syncthreads();
#pragma unroll
        for (int k = 0; k < 64; k++) {
            float w = Wsh[t * 65 + k];
#pragma unroll
            for (int i = 0; i < PTM; i++) acc[i] = fmaf(Hsh[i][k], w, acc[i]);
        }
        __syncthreads();
    }
#pragma unroll
    for (int i = 0; i < PTM; i++) proj[(i0 + i) * PROJC + t] = acc[i];
}

// ---------------------------------------------------------------------------
__device__ __forceinline__ float combine2(float a, float b, int mask, int l) {
    float sel = (l & mask) ? a : b;
    float t = __shfl_xor_sync(0xffffffffu, sel, mask);
    return (l & mask) ? (b + t) : (a + t);
}

__device__ __forceinline__ void cp16(uint32_t s, const void* g) {
    asm volatile("cp.async.cg.shared.global [%0], [%1], 16;\n" :: "r"(s), "l"(g));
}

// ---------------------------------------------------------------------------
// Kernel 2: fused scores + max-free online softmax + P@V.
// Warp-private cp.async pipeline: warp w streams D[i0..i0+7, j=w+16k, :]
// into its own 4-stage smem ring; no block barriers in the main loop.
// Lane l owns dims {2l, 2l+1}. Cross-warp combine in a short epilogue.
// ---------------------------------------------------------------------------
__global__ __launch_bounds__(512, 1) void attn_kernel(const float* __restrict__ D,
                                                      const float* __restrict__ proj,
                                                      float* __restrict__ out) {
    extern __shared__ float smem[];
    const int t  = threadIdx.x;
    const int w  = t >> 5;
    const int l  = t & 31;
    const int i0 = blockIdx.x * TM;

    float* wbuf    = smem + w * (STAGES * 512);            // 4 stages x 2KB
    float* scratch = smem + NW * STAGES * 512 + w * 8;     // 8 scores per warp
    const uint32_t wbuf_s = (uint32_t)__cvta_generic_to_shared(wbuf);

    const float scale = 0.08838834764831845f;              // 1/sqrt(DK+DR)

    // Pre-scaled Q,R fragments for the tile's 8 rows (dims 2l,2l+1).
    float2 q2[TM], r2[TM];
#pragma unroll
    for (int i = 0; i < TM; i++) {
        const float* row = proj + (size_t)(i0 + i) * PROJC;
        float2 qq = *(const float2*)(row + 2 * l);
        float2 rr = *(const float2*)(row + 192 + 2 * l);
        q2[i] = make_float2(qq.x * scale, qq.y * scale);
        r2[i] = make_float2(rr.x * scale, rr.y * scale);
    }

    // Prologue: fill all 4 stages.  Stage holds 8 rows x 256B; lane l copies
    // 4 x 16B chunks: flat idx = l + 32c -> row = idx>>4, u = idx&15.
#pragma unroll
    for (int s = 0; s < STAGES; s++) {
        int j = w + 16 * s;
#pragma unroll
        for (int c = 0; c < 4; c++) {
            int idx = l + 32 * c;
            const float* g = D + (((size_t)(i0 + (idx >> 4)) * N + j) << 6) + ((idx & 15) << 2);
            cp16(wbuf_s + (uint32_t)(s * 2048 + idx * 16), g);
        }
        asm volatile("cp.async.commit_group;\n" ::: "memory");
    }

    // Prefetch K/V for j = w.
    float2 kv = *(const float2*)(proj + (size_t)w * PROJC + 64 + 2 * l);
    float2 vv = *(const float2*)(proj + (size_t)w * PROJC + 128 + 2 * l);

    const int irow = ((l >> 4) & 1) | (((l >> 3) & 1) << 1) | (((l >> 2) & 1) << 2);

    float  sum[TM];
    float2 acc[TM];
#pragma unroll
    for (int i = 0; i < TM; i++) { sum[i] = 0.f; acc[i] = make_float2(0.f, 0.f); }

    for (int k = 0; k < NIT; k++) {
        asm volatile("cp.async.wait_group 3;\n" ::: "memory");
        __syncwarp();

        const float* Db = wbuf + (k & 3) * 512;
        float v[TM];
#pragma unroll
        for (int r = 0; r < TM; r++) {
            float2 dv = *(const float2*)(Db + r * 64 + 2 * l);
            v[r] = fmaf(dv.x, r2[r].x,
                   fmaf(dv.y, r2[r].y,
                   fmaf(kv.x, q2[r].x, kv.y * q2[r].y)));
        }
        float c0 = combine2(v[0], v[1], 16, l);
        float c1 = combine2(v[2], v[3], 16, l);
        float c2 = combine2(v[4], v[5], 16, l);
        float c3 = combine2(v[6], v[7], 16, l);
        float d0 = combine2(c0, c1, 8, l);
        float d1 = combine2(c2, c3, 8, l);
        float e0 = combine2(d0, d1, 4, l);
        float f  = e0 + __shfl_xor_sync(0xffffffffu, e0, 2);
        float g  = f + __shfl_xor_sync(0xffffffffu, f, 1);
        if ((l & 3) == 0) scratch[irow] = g;
        __syncwarp();

        // Refill the stage we just consumed (j = w + 16*(k+4)).
        if (k + STAGES < NIT) {
            int j = w + 16 * (k + STAGES);
#pragma unroll
            for (int c = 0; c < 4; c++) {
                int idx = l + 32 * c;
                const float* gp = D + (((size_t)(i0 + (idx >> 4)) * N + j) << 6) + ((idx & 15) << 2);
                cp16(wbuf_s + (uint32_t)((k & 3) * 2048 + idx * 16), gp);
            }
        }
        asm volatile("cp.async.commit_group;\n" ::: "memory");

        // Scores (replicated across lanes) + prefetch next K/V.
        float4 s0 = *(const float4*)scratch;
        float4 s1 = *(const float4*)(scratch + 4);
        int jn = (w + 16 * (k + 1)) & (N - 1);
        float2 kn = *(const float2*)(proj + (size_t)jn * PROJC + 64 + 2 * l);
        float2 vn = *(const float2*)(proj + (size_t)jn * PROJC + 128 + 2 * l);

        float p;
        p = __expf(s0.x); sum[0] += p; acc[0].x = fmaf(p, vv.x, acc[0].x); acc[0].y = fmaf(p, vv.y, acc[0].y);
        p = __expf(s0.y); sum[1] += p; acc[1].x = fmaf(p, vv.x, acc[1].x); acc[1].y = fmaf(p, vv.y, acc[1].y);
        p = __expf(s0.z); sum[2] += p; acc[2].x = fmaf(p, vv.x, acc[2].x); acc[2].y = fmaf(p, vv.y, acc[2].y);
        p = __expf(s0.w); sum[3] += p; acc[3].x = fmaf(p, vv.x, acc[3].x); acc[3].y = fmaf(p, vv.y, acc[3].y);
        p = __expf(s1.x); sum[4] += p; acc[4].x = fmaf(p, vv.x, acc[4].x); acc[4].y = fmaf(p, vv.y, acc[4].y);
        p = __expf(s1.y); sum[5] += p; acc[5].x = fmaf(p, vv.x, acc[5].x); acc[5].y = fmaf(p, vv.y, acc[5].y);
        p = __expf(s1.z); sum[6] += p; acc[6].x = fmaf(p, vv.x, acc[6].x); acc[6].y = fmaf(p, vv.y, acc[6].y);
        p = __expf(s1.w); sum[7] += p; acc[7].x = fmaf(p, vv.x, acc[7].x); acc[7].y = fmaf(p, vv.y, acc[7].y);

        kv = kn; vv = vn;
    }

    // ---------------- epilogue: combine the 16 warps' partials ----------------
    __syncthreads();
    float* accsh = smem;                   // [16][8][64]
    float* sumsh = smem + NW * TM * 64;    // [16][8]
#pragma unroll
    for (int r = 0; r < TM; r++)
        *(float2*)(accsh + ((w * TM + r) * 64) + 2 * l) = acc[r];
    if (l == 0) {
#pragma unroll
        for (int r = 0; r < TM; r++) sumsh[w * TM + r] = sum[r];
    }
    __syncthreads();
    if (w < TM) {
        float2 tot = make_float2(0.f, 0.f);
        float  st  = 0.f;
#pragma unroll
        for (int ww = 0; ww < NW; ww++) {
            float2 a = *(const float2*)(accsh + ((ww * TM + w) * 64) + 2 * l);
            tot.x += a.x; tot.y += a.y;
            st += sumsh[ww * TM + w];
        }
        float inv = 1.0f / st;
        *(float2*)(out + (size_t)(i0 + w) * 64 + 2 * l) = make_float2(tot.x * inv, tot.y * inv);
    }
}

// ---------------------------------------------------------------------------
extern "C" void kernel_launch(void* const* d_in, const int* in_sizes, int n_in,
                              void* d_out, int out_size) {
    const float* H = (const float*)d_in[0];
    const float* D = (const float*)d_in[1];
    const float* W = (const float*)d_in[2];
    float* out = (float*)d_out;

    const int proj_smem = 256 * 65 * 4;                               // 66,560 B
    const int attn_smem = (NW * STAGES * 512 + NW * 8) * 4;           // 131,584 B
    cudaFuncSetAttribute(proj_kernel, cudaFuncAttributeMaxDynamicSharedMemorySize, proj_smem);
    cudaFuncSetAttribute(attn_kernel, cudaFuncAttributeMaxDynamicSharedMemorySize, attn_smem);

    void* proj_ptr = nullptr;
    cudaGetSymbolAddress(&proj_ptr, g_proj);
    float* proj = (float*)proj_ptr;

    proj_kernel<<<N / PTM, 256, proj_smem>>>(H, W, proj);
    attn_kernel<<<N / TM, 512, attn_smem>>>(D, proj, out);
}

// round 4
// speedup vs baseline: 2.0156x; 1.0632x over previous
#include <cuda_runtime.h>
#include <cstdint>

#define N      2048
#define DIN    256
#define PROJC  256
#define PTM    8           // proj kernel row tile
#define TM     8           // attn rows per CTA
#define NW     8           // warps per attn CTA
#define STAGES 4
#define NIT    (N / NW)    // 256 iterations, j = w + 8k

// 2 MB scratch for projection output: cols = [Q(64) | K(64) | V(64) | R(64)]
__device__ float g_proj[N * PROJC];

// ---------------------------------------------------------------------------
// Kernel 1: proj = H @ W^T
// ---------------------------------------------------------------------------
__global__ __launch_bounds__(256) void proj_kernel(const float* __restrict__ H,
                                                   const float* __restrict__ W,
                                                   float* __restrict__ proj) {
    __shared__ float Hsh[PTM][64];
    extern __shared__ float Wsh[];          // [256][65]
    const int t  = threadIdx.x;
    const int i0 = blockIdx.x * PTM;

    float acc[PTM];
#pragma unroll
    for (int i = 0; i < PTM; i++) acc[i] = 0.f;

    for (int kc = 0; kc < DIN; kc += 64) {
        if (t < PTM * 64 / 4) {
#pragma unroll
            for (int r = 0; r < 4; r++) {
                int idx = t + r * 128;
                if (idx < PTM * 64)
                    Hsh[idx >> 6][idx & 63] = H[(i0 + (idx >> 6)) * DIN + kc + (idx & 63)];
            }
        }
#pragma unroll 8
        for (int r = 0; r < 64; r++) {
            int idx = t + r * 256;
            Wsh[(idx >> 6) * 65 + (idx & 63)] = W[(idx >> 6) * DIN + kc + (idx & 63)];
        }
        __syncthreads();
#pragma unroll
        for (int k = 0; k < 64; k++) {
            float w = Wsh[t * 65 + k];
#pragma unroll
            for (int i = 0; i < PTM; i++) acc[i] = fmaf(Hsh[i][k], w, acc[i]);
        }
        __syncthreads();
    }
#pragma unroll
    for (int i = 0; i < PTM; i++) proj[(i0 + i) * PROJC + t] = acc[i];
}

// ---------------------------------------------------------------------------
__device__ __forceinline__ float combine2(float a, float b, int mask, int l) {
    float sel = (l & mask) ? a : b;
    float t = __shfl_xor_sync(0xffffffffu, sel, mask);
    return (l & mask) ? (b + t) : (a + t);
}

__device__ __forceinline__ void cp16(uint32_t s, const void* g) {
    asm volatile("cp.async.cg.shared.global [%0], [%1], 16;\n" :: "r"(s), "l"(g));
}

// ---------------------------------------------------------------------------
// Kernel 2: fused scores + max-free online softmax + P@V.
// 8 warps / 256 threads, 2 CTAs/SM -> whole grid resident in one wave.
// Warp w streams D[i0..i0+7, j=w+8k, :] through a private 4-stage ring.
// Lane l owns dims {2l, 2l+1}. Cross-warp combine in a short epilogue.
// ---------------------------------------------------------------------------
__global__ __launch_bounds__(256, 2) void attn_kernel(const float* __restrict__ D,
                                                      const float* __restrict__ proj,
                                                      float* __restrict__ out) {
    extern __shared__ float smem[];
    const int t  = threadIdx.x;
    const int w  = t >> 5;
    const int l  = t & 31;
    const int i0 = blockIdx.x * TM;

    float* wbuf    = smem + w * (STAGES * 512);            // 4 stages x 2KB
    float* scratch = smem + NW * STAGES * 512 + w * 8;     // 8 scores per warp
    const uint32_t wbuf_s = (uint32_t)__cvta_generic_to_shared(wbuf);

    const float scale = 0.08838834764831845f;              // 1/sqrt(DK+DR)

    // Pre-scaled Q,R fragments for the tile's 8 rows (dims 2l,2l+1).
    float2 q2[TM], r2[TM];
#pragma unroll
    for (int i = 0; i < TM; i++) {
        const float* row = proj + (size_t)(i0 + i) * PROJC;
        float2 qq = *(const float2*)(row + 2 * l);
        float2 rr = *(const float2*)(row + 192 + 2 * l);
        q2[i] = make_float2(qq.x * scale, qq.y * scale);
        r2[i] = make_float2(rr.x * scale, rr.y * scale);
    }

    // Prologue: fill all 4 stages. Stage = 8 rows x 256B; lane l copies
    // 4 x 16B chunks: flat idx = l + 32c -> row = idx>>4, u = idx&15.
#pragma unroll
    for (int s = 0; s < STAGES; s++) {
        int j = w + NW * s;
#pragma unroll
        for (int c = 0; c < 4; c++) {
            int idx = l + 32 * c;
            const float* g = D + (((size_t)(i0 + (idx >> 4)) * N + j) << 6) + ((idx & 15) << 2);
            cp16(wbuf_s + (uint32_t)(s * 2048 + idx * 16), g);
        }
        asm volatile("cp.async.commit_group;\n" ::: "memory");
    }

    // Prefetch K/V for j = w.
    float2 kv = *(const float2*)(proj + (size_t)w * PROJC + 64 + 2 * l);
    float2 vv = *(const float2*)(proj + (size_t)w * PROJC + 128 + 2 * l);

    const int irow = ((l >> 4) & 1) | (((l >> 3) & 1) << 1) | (((l >> 2) & 1) << 2);

    float  sum[TM];
    float2 acc[TM];
#pragma unroll
    for (int i = 0; i < TM; i++) { sum[i] = 0.f; acc[i] = make_float2(0.f, 0.f); }

    for (int k = 0; k < NIT; k++) {
        asm volatile("cp.async.wait_group 3;\n" ::: "memory");
        __syncwarp();

        const float* Db = wbuf + (k & 3) * 512;
        float v[TM];
#pragma unroll
        for (int r = 0; r < TM; r++) {
            float2 dv = *(const float2*)(Db + r * 64 + 2 * l);
            v[r] = fmaf(dv.x, r2[r].x,
                   fmaf(dv.y, r2[r].y,
                   fmaf(kv.x, q2[r].x, kv.y * q2[r].y)));
        }
        float c0 = combine2(v[0], v[1], 16, l);
        float c1 = combine2(v[2], v[3], 16, l);
        float c2 = combine2(v[4], v[5], 16, l);
        float c3 = combine2(v[6], v[7], 16, l);
        float d0 = combine2(c0, c1, 8, l);
        float d1 = combine2(c2, c3, 8, l);
        float e0 = combine2(d0, d1, 4, l);
        float f  = e0 + __shfl_xor_sync(0xffffffffu, e0, 2);
        float g  = f + __shfl_xor_sync(0xffffffffu, f, 1);
        if ((l & 3) == 0) scratch[irow] = g;
        __syncwarp();

        // Refill the stage we just consumed (j = w + 8*(k+4)).
        if (k + STAGES < NIT) {
            int j = w + NW * (k + STAGES);
#pragma unroll
            for (int c = 0; c < 4; c++) {
                int idx = l + 32 * c;
                const float* gp = D + (((size_t)(i0 + (idx >> 4)) * N + j) << 6) + ((idx & 15) << 2);
                cp16(wbuf_s + (uint32_t)((k & 3) * 2048 + idx * 16), gp);
            }
        }
        asm volatile("cp.async.commit_group;\n" ::: "memory");

        // Scores (replicated across lanes) + prefetch next K/V.
        float4 s0 = *(const float4*)scratch;
        float4 s1 = *(const float4*)(scratch + 4);
        int jn = (w + NW * (k + 1)) & (N - 1);
        float2 kn = *(const float2*)(proj + (size_t)jn * PROJC + 64 + 2 * l);
        float2 vn = *(const float2*)(proj + (size_t)jn * PROJC + 128 + 2 * l);

        float p;
        p = __expf(s0.x); sum[0] += p; acc[0].x = fmaf(p, vv.x, acc[0].x); acc[0].y = fmaf(p, vv.y, acc[0].y);
        p = __expf(s0.y); sum[1] += p; acc[1].x = fmaf(p, vv.x, acc[1].x); acc[1].y = fmaf(p, vv.y, acc[1].y);
        p = __expf(s0.z); sum[2] += p; acc[2].x = fmaf(p, vv.x, acc[2].x); acc[2].y = fmaf(p, vv.y, acc[2].y);
        p = __expf(s0.w); sum[3] += p; acc[3].x = fmaf(p, vv.x, acc[3].x); acc[3].y = fmaf(p, vv.y, acc[3].y);
        p = __expf(s1.x); sum[4] += p; acc[4].x = fmaf(p, vv.x, acc[4].x); acc[4].y = fmaf(p, vv.y, acc[4].y);
        p = __expf(s1.y); sum[5] += p; acc[5].x = fmaf(p, vv.x, acc[5].x); acc[5].y = fmaf(p, vv.y, acc[5].y);
        p = __expf(s1.z); sum[6] += p; acc[6].x = fmaf(p, vv.x, acc[6].x); acc[6].y = fmaf(p, vv.y, acc[6].y);
        p = __expf(s1.w); sum[7] += p; acc[7].x = fmaf(p, vv.x, acc[7].x); acc[7].y = fmaf(p, vv.y, acc[7].y);

        kv = kn; vv = vn;
    }

    // ---------------- epilogue: combine the 8 warps' partials ----------------
    __syncthreads();
    float* accsh = smem;                   // [8][8][64]
    float* sumsh = smem + NW * TM * 64;    // [8][8]
#pragma unroll
    for (int r = 0; r < TM; r++)
        *(float2*)(accsh + ((w * TM + r) * 64) + 2 * l) = acc[r];
    if (l == 0) {
#pragma unroll
        for (int r = 0; r < TM; r++) sumsh[w * TM + r] = sum[r];
    }
    __syncthreads();
    {
        float2 tot = make_float2(0.f, 0.f);
        float  st  = 0.f;
#pragma unroll
        for (int ww = 0; ww < NW; ww++) {
            float2 a = *(const float2*)(accsh + ((ww * TM + w) * 64) + 2 * l);
            tot.x += a.x; tot.y += a.y;
            st += sumsh[ww * TM + w];
        }
        float inv = 1.0f / st;
        *(float2*)(out + (size_t)(i0 + w) * 64 + 2 * l) = make_float2(tot.x * inv, tot.y * inv);
    }
}

// ---------------------------------------------------------------------------
extern "C" void kernel_launch(void* const* d_in, const int* in_sizes, int n_in,
                              void* d_out, int out_size) {
    const float* H = (const float*)d_in[0];
    const float* D = (const float*)d_in[1];
    const float* W = (const float*)d_in[2];
    float* out = (float*)d_out;

    const int proj_smem = 256 * 65 * 4;                               // 66,560 B
    const int attn_smem = (NW * STAGES * 512 + NW * 8) * 4;           // 65,792 B
    cudaFuncSetAttribute(proj_kernel, cudaFuncAttributeMaxDynamicSharedMemorySize, proj_smem);
    cudaFuncSetAttribute(attn_kernel, cudaFuncAttributeMaxDynamicSharedMemorySize, attn_smem);

    void* proj_ptr = nullptr;
    cudaGetSymbolAddress(&proj_ptr, g_proj);
    float* proj = (float*)proj_ptr;

    proj_kernel<<<N / PTM, 256, proj_smem>>>(H, W, proj);
    attn_kernel<<<N / TM, 256, attn_smem>>>(D, proj, out);
}